// round 6
// baseline (speedup 1.0000x reference)
#include <cuda_runtime.h>

#define NN 1000
#define DD 128
#define NEGV (-1e9f)
typedef unsigned long long u64;

static __device__ __forceinline__ u64 pack2(float a, float b) {
    u64 r; asm("mov.b64 %0, {%1, %2};" : "=l"(r) : "f"(a), "f"(b)); return r;
}
static __device__ __forceinline__ u64 packdup(float a) { return pack2(a, a); }
static __device__ __forceinline__ u64 fma2(u64 a, u64 b, u64 c) {
    u64 d; asm("fma.rn.f32x2 %0, %1, %2, %3;" : "=l"(d) : "l"(a), "l"(b), "l"(c)); return d;
}
static __device__ __forceinline__ float2 unpack2(u64 v) {
    float lo, hi; asm("mov.b64 {%0, %1}, %2;" : "=f"(lo), "=f"(hi) : "l"(v));
    return make_float2(lo, hi);
}
static __device__ __forceinline__ float tanh_fast(float x) {
    float y; asm("tanh.approx.f32 %0, %1;" : "=f"(y) : "f"(x)); return y;
}
static __device__ __forceinline__ void cp16(float* dst, const float* src) {
    unsigned sa = (unsigned)__cvta_generic_to_shared(dst);
    asm volatile("cp.async.cg.shared.global [%0], [%1], 16;" :: "r"(sa), "l"(src));
}

// smem word offsets
#define O_COMPAT 0          // 8000 (later: phase2 partials 4096 / s_lg 1000)
#define O_BUF    8000       // 9216 = 2 x (128*36) stage buffers (later: s_at 8000)
#define O_QT     17216      // 1040 = 4 pairs * 260 (u64 per dim, padded)
#define O_MEAN   18256
#define O_Q      18384
#define O_EF     18512
#define O_EL     18640
#define O_HEADS  18768
#define O_GL     18896
#define O_GT     19024
#define O_EBAR   19152      // 1024
#define O_RED    20176      // 32
#define SM_WORDS 20208      // 80832 bytes

__global__ __launch_bounds__(512, 2) void attn_v5(
    const float* __restrict__ emb, const float* __restrict__ Wn,
    const float* __restrict__ Wf, const float* __restrict__ Ws,
    const float* __restrict__ Wo, const int* __restrict__ fidx,
    const int* __restrict__ lidx, const int* __restrict__ mask,
    float* __restrict__ out)
{
    extern __shared__ float sm[];
    float* s_compat = sm + O_COMPAT;
    float* s_buf    = sm + O_BUF;
    float* s_QT     = sm + O_QT;
    float* s_mean   = sm + O_MEAN;
    float* s_q      = sm + O_Q;
    float* s_ef     = sm + O_EF;
    float* s_el     = sm + O_EL;
    float* s_heads  = sm + O_HEADS;
    float* s_gl     = sm + O_GL;
    float* s_gt     = sm + O_GT;
    float* s_ebar   = sm + O_EBAR;
    float* s_red    = sm + O_RED;

    const int b = blockIdx.x, t = threadIdx.x;
    const int lane = t & 31, warp = t >> 5;
    const float* embB = emb + (size_t)b * NN * DD;
    const int* mkB = mask + (size_t)b * NN;

    // chunk k = T*4+c : rows [T*128, T*128+128), dims [c*32, c*32+32)
    auto prefetchT = [&](int k) {
        int T = k >> 2, c = k & 3;
        float* dst = s_buf + (k & 1) * 4608;
        int idx = t * 2;
        int row = idx >> 3, seg = idx & 7;       // seg in {0,2,4,6}
        int gr = T * 128 + row; if (gr > NN - 1) gr = NN - 1;
        const float* src = embB + (size_t)gr * DD + c * 32 + seg * 4;
        cp16(dst + row * 36 + seg * 4, src);
        cp16(dst + row * 36 + (seg + 1) * 4, src + 4);
        asm volatile("cp.async.commit_group;");
    };

    // prologue: phase-1 chunk 0 in flight during phase 0
    prefetchT(0);

    // ---- Phase 0: mean (4 row-groups, 16 rows in flight) + first/last ----
    {
        int d = t & 127, g = t >> 7;
        const float* E = embB + d;
        float a0 = 0.f, a1 = 0.f, a2 = 0.f, a3 = 0.f;
        int n = g;
        for (; n + 12 < NN; n += 16) {
            a0 += E[(size_t)n * DD];
            a1 += E[(size_t)(n + 4) * DD];
            a2 += E[(size_t)(n + 8) * DD];
            a3 += E[(size_t)(n + 12) * DD];
        }
        for (; n < NN; n += 4) a0 += E[(size_t)n * DD];
        s_compat[g * DD + d] = (a0 + a1) + (a2 + a3);
    }
    if (t < DD)       s_ef[t] = embB[(size_t)fidx[b] * DD + t];
    else if (t < 256) s_el[t - DD] = embB[(size_t)lidx[b] * DD + (t - DD)];
    __syncthreads();
    if (t < DD)
        s_mean[t] = (s_compat[t] + s_compat[DD + t] + s_compat[2 * DD + t]
                     + s_compat[3 * DD + t]) * (1.0f / NN);
    __syncthreads();

    // ---- Phase 0b: q = mean@Wf + [ef;el]@Ws ----
    if (t < DD) {
        float acc = 0.f;
        #pragma unroll 4
        for (int i = 0; i < DD; i++) acc += s_mean[i] * Wf[i * DD + t];
        #pragma unroll 4
        for (int i = 0; i < DD; i++) acc += s_ef[i] * Ws[i * DD + t];
        #pragma unroll 4
        for (int i = 0; i < DD; i++) acc += s_el[i] * Ws[(DD + i) * DD + t];
        s_q[t] = acc;
    }
    __syncthreads();

    // ---- Phase 0c: qt, layout [pair p][dim d] as u64 (stride 260 floats) ----
    if (t < 256) {
        int d = t >> 1, h0 = (t & 1) * 4;
        #pragma unroll
        for (int h = h0; h < h0 + 4; h++) {
            const float* w = Wn + d * 384 + h * 16;
            const float* qq = s_q + h * 16;
            float acc = 0.f;
            #pragma unroll
            for (int k = 0; k < 16; k++) acc += w[k] * qq[k];
            s_QT[(h >> 1) * 260 + d * 2 + (h & 1)] = acc * 0.25f;
        }
    }

    // ---- Phase 1: compat, cp.async 2-stage pipeline ----
    {
        const int rl = t >> 2, p = t & 3;
        const u64* qtp = (const u64*)(s_QT + p * 260);
        u64 acc = 0;
        for (int k = 0; k < 32; k++) {
            if (k + 1 < 32) {
                prefetchT(k + 1);
                asm volatile("cp.async.wait_group 1;");
            } else {
                asm volatile("cp.async.wait_group 0;");
            }
            __syncthreads();
            const float* bp = s_buf + (k & 1) * 4608 + rl * 36;
            int c = k & 3;
            #pragma unroll
            for (int j = 0; j < 8; j++) {
                float4 e = *(const float4*)(bp + j * 4);
                int d = c * 32 + j * 4;
                ulonglong2 q01 = *(const ulonglong2*)(qtp + d);
                ulonglong2 q23 = *(const ulonglong2*)(qtp + d + 2);
                acc = fma2(packdup(e.x), q01.x, acc);
                acc = fma2(packdup(e.y), q01.y, acc);
                acc = fma2(packdup(e.z), q23.x, acc);
                acc = fma2(packdup(e.w), q23.y, acc);
            }
            if (c == 3) {
                int row = (k >> 2) * 128 + rl;
                if (row < NN) {
                    int mk = mkB[row];
                    float2 v = unpack2(acc);
                    s_compat[(2 * p) * NN + row]     = mk ? NEGV : v.x;
                    s_compat[(2 * p + 1) * NN + row] = mk ? NEGV : v.y;
                }
                acc = 0;
            }
            __syncthreads();
        }
    }

    // ---- Phase 1b: per-head softmax, 2 warps per head ----
    {
        int h = warp >> 1, seg = warp & 1;
        const float* row = s_compat + h * NN;
        float mx = -1e30f;
        for (int n = seg * 32 + lane; n < NN; n += 64) mx = fmaxf(mx, row[n]);
        #pragma unroll
        for (int o = 16; o > 0; o >>= 1) mx = fmaxf(mx, __shfl_xor_sync(0xffffffffu, mx, o));
        if (lane == 0) s_red[warp] = mx;
        __syncthreads();
        float hm = fmaxf(s_red[2 * h], s_red[2 * h + 1]);
        float sme = 0.f;
        for (int n = seg * 32 + lane; n < NN; n += 64) sme += __expf(row[n] - hm);
        #pragma unroll
        for (int o = 16; o > 0; o >>= 1) sme += __shfl_xor_sync(0xffffffffu, sme, o);
        if (lane == 0) s_red[16 + warp] = sme;
        __syncthreads();
        float inv = 1.0f / (s_red[16 + 2 * h] + s_red[16 + 2 * h + 1]);
        for (int n = seg * 32 + lane; n < NN; n += 64)
            s_buf[n * 8 + h] = __expf(row[n] - hm) * inv;   // s_at[n][8]
    }
    __syncthreads();

    // ---- Phase 2: ebar, 4 row-groups, attn broadcast, unroll x4 ----
    {
        int dim = t & 127, g = t >> 7;
        const float* E = embB + dim;
        u64 a0 = 0, a1 = 0, a2 = 0, a3 = 0;
        int n = g;
        for (; n + 12 < NN; n += 16) {
            float e0 = E[(size_t)n * DD];
            float e1 = E[(size_t)(n + 4) * DD];
            float e2 = E[(size_t)(n + 8) * DD];
            float e3 = E[(size_t)(n + 12) * DD];
            const u64* t0 = (const u64*)(s_buf + n * 8);
            const u64* t1 = (const u64*)(s_buf + (n + 4) * 8);
            const u64* t2 = (const u64*)(s_buf + (n + 8) * 8);
            const u64* t3 = (const u64*)(s_buf + (n + 12) * 8);
            u64 d0 = packdup(e0), d1 = packdup(e1), d2 = packdup(e2), d3 = packdup(e3);
            a0 = fma2(d0, t0[0], a0); a1 = fma2(d0, t0[1], a1);
            a2 = fma2(d0, t0[2], a2); a3 = fma2(d0, t0[3], a3);
            a0 = fma2(d1, t1[0], a0); a1 = fma2(d1, t1[1], a1);
            a2 = fma2(d1, t1[2], a2); a3 = fma2(d1, t1[3], a3);
            a0 = fma2(d2, t2[0], a0); a1 = fma2(d2, t2[1], a1);
            a2 = fma2(d2, t2[2], a2); a3 = fma2(d2, t2[3], a3);
            a0 = fma2(d3, t3[0], a0); a1 = fma2(d3, t3[1], a1);
            a2 = fma2(d3, t3[2], a2); a3 = fma2(d3, t3[3], a3);
        }
        for (; n < NN; n += 4) {
            u64 ed = packdup(E[(size_t)n * DD]);
            const u64* at = (const u64*)(s_buf + n * 8);
            a0 = fma2(ed, at[0], a0); a1 = fma2(ed, at[1], a1);
            a2 = fma2(ed, at[2], a2); a3 = fma2(ed, at[3], a3);
        }
        __syncthreads();   // all s_at reads done; s_buf & compat free
        // start phase-3 chunk 0 while we finish the small matvecs
        prefetchT(0);
        float2 f0 = unpack2(a0), f1 = unpack2(a1), f2 = unpack2(a2), f3 = unpack2(a3);
        float* pp = s_compat + g * 1024 + dim;   // partials [g][h][128]
        pp[0] = f0.x; pp[128] = f0.y; pp[256] = f1.x; pp[384] = f1.y;
        pp[512] = f2.x; pp[640] = f2.y; pp[768] = f3.x; pp[896] = f3.y;
    }
    __syncthreads();
    {
        s_ebar[t] = (s_compat[t] + s_compat[1024 + t])
                  + (s_compat[2048 + t] + s_compat[3072 + t]);
        int i2 = t + 512;
        s_ebar[i2] = (s_compat[i2] + s_compat[1024 + i2])
                   + (s_compat[2048 + i2] + s_compat[3072 + i2]);
    }
    __syncthreads();

    // ---- Phase 2b: heads -> glimpse -> gtilde ----
    if (t < DD) {
        int h = t >> 4;
        const float* eb = s_ebar + h * DD;
        float acc = 0.f;
        #pragma unroll 4
        for (int d = 0; d < DD; d++) acc += eb[d] * Wn[d * 384 + 128 + t];
        s_heads[t] = acc;
    }
    __syncthreads();
    if (t < DD) {
        float acc = 0.f;
        #pragma unroll 4
        for (int i = 0; i < DD; i++) acc += s_heads[i] * Wo[i * DD + t];
        s_gl[t] = acc;
    }
    __syncthreads();
    if (t < DD) {
        const float* w = Wn + t * 384 + 256;
        float acc = 0.f;
        #pragma unroll 4
        for (int j = 0; j < DD; j++) acc += w[j] * s_gl[j];
        s_gt[t] = acc * 0.08838834764831845f;
    }
    __syncthreads();

    // ---- Phase 3: logits, cp.async 2-stage pipeline, 4 threads/row ----
    float* s_lg = s_compat;
    float lmax = -1e30f;
    {
        const int rl = t >> 2, p = t & 3;
        u64 acc = 0;
        for (int k = 0; k < 32; k++) {
            if (k + 1 < 32) {
                prefetchT(k + 1);
                asm volatile("cp.async.wait_group 1;");
            } else {
                asm volatile("cp.async.wait_group 0;");
            }
            __syncthreads();
            const float* bp = s_buf + (k & 1) * 4608 + rl * 36 + p * 8;
            int c = k & 3;
            const u64* gtp = (const u64*)s_gt + c * 16 + p * 4;
            float4 e0 = *(const float4*)(bp);
            float4 e1 = *(const float4*)(bp + 4);
            acc = fma2(pack2(e0.x, e0.y), gtp[0], acc);
            acc = fma2(pack2(e0.z, e0.w), gtp[1], acc);
            acc = fma2(pack2(e1.x, e1.y), gtp[2], acc);
            acc = fma2(pack2(e1.z, e1.w), gtp[3], acc);
            if (c == 3) {
                float2 v = unpack2(acc);
                float s = v.x + v.y;
                s += __shfl_xor_sync(0xffffffffu, s, 1);
                s += __shfl_xor_sync(0xffffffffu, s, 2);
                int row = (k >> 2) * 128 + rl;
                if (p == 0 && row < NN) {
                    float vv = tanh_fast(s) * 10.0f;
                    if (mkB[row] != 0) vv = NEGV;
                    s_lg[row] = vv;
                    lmax = fmaxf(lmax, vv);
                }
                acc = 0;
            }
            __syncthreads();
        }
    }
    // ---- log-softmax over 1000 ----
    #pragma unroll
    for (int o = 16; o > 0; o >>= 1) lmax = fmaxf(lmax, __shfl_xor_sync(0xffffffffu, lmax, o));
    if (lane == 0) s_red[warp] = lmax;
    __syncthreads();
    float bmax = s_red[0];
    #pragma unroll
    for (int w = 1; w < 16; w++) bmax = fmaxf(bmax, s_red[w]);
    float ls = 0.f;
    for (int n = t; n < NN; n += 512) ls += __expf(s_lg[n] - bmax);
    #pragma unroll
    for (int o = 16; o > 0; o >>= 1) ls += __shfl_xor_sync(0xffffffffu, ls, o);
    if (lane == 0) s_red[16 + warp] = ls;
    __syncthreads();
    float tot = s_red[16];
    #pragma unroll
    for (int w = 1; w < 16; w++) tot += s_red[16 + w];
    float logZ = bmax + logf(tot);
    float* outB = out + (size_t)b * NN;
    for (int n = t; n < NN; n += 512) outB[n] = s_lg[n] - logZ;
}

extern "C" void kernel_launch(void* const* d_in, const int* in_sizes, int n_in,
                              void* d_out, int out_size) {
    const float* emb = (const float*)d_in[0];
    const float* Wn  = (const float*)d_in[1];
    const float* Wf  = (const float*)d_in[2];
    const float* Ws  = (const float*)d_in[3];
    const float* Wo  = (const float*)d_in[4];
    const int* fidx  = (const int*)d_in[5];
    const int* lidx  = (const int*)d_in[6];
    const int* mask  = (const int*)d_in[7];
    float* out = (float*)d_out;
    cudaFuncSetAttribute(attn_v5, cudaFuncAttributeMaxDynamicSharedMemorySize, SM_WORDS * 4);
    attn_v5<<<256, 512, SM_WORDS * 4>>>(emb, Wn, Wf, Ws, Wo, fidx, lidx, mask, out);
}

// round 7
// speedup vs baseline: 1.1457x; 1.1457x over previous
#include <cuda_runtime.h>

#define NN 1000
#define DD 128
#define NEGV (-1e9f)
typedef unsigned long long u64;

static __device__ __forceinline__ u64 pack2(float a, float b) {
    u64 r; asm("mov.b64 %0, {%1, %2};" : "=l"(r) : "f"(a), "f"(b)); return r;
}
static __device__ __forceinline__ u64 packdup(float a) { return pack2(a, a); }
static __device__ __forceinline__ u64 fma2(u64 a, u64 b, u64 c) {
    u64 d; asm("fma.rn.f32x2 %0, %1, %2, %3;" : "=l"(d) : "l"(a), "l"(b), "l"(c)); return d;
}
static __device__ __forceinline__ float2 unpack2(u64 v) {
    float lo, hi; asm("mov.b64 {%0, %1}, %2;" : "=f"(lo), "=f"(hi) : "l"(v));
    return make_float2(lo, hi);
}
static __device__ __forceinline__ float tanh_fast(float x) {
    float y; asm("tanh.approx.f32 %0, %1;" : "=f"(y) : "f"(x)); return y;
}

// smem word offsets
#define O_COMPAT 0          // 8000 (later: phase2 partials 4096 / s_lg 1000)
#define O_BUF    8000       // 9216 = 256*36 stage buffer (later: s_at 8000)
#define O_QT     17216      // 1024 = qt[d][8]
#define O_MEAN   18240
#define O_Q      18368
#define O_EF     18496
#define O_EL     18624
#define O_HEADS  18752
#define O_GL     18880
#define O_GT     19008
#define O_EBAR   19136      // 1024
#define O_RED    20160      // 32
#define SM_WORDS 20192      // 80768 bytes

__global__ __launch_bounds__(512, 2) void attn_v6(
    const float* __restrict__ emb, const float* __restrict__ Wn,
    const float* __restrict__ Wf, const float* __restrict__ Ws,
    const float* __restrict__ Wo, const int* __restrict__ fidx,
    const int* __restrict__ lidx, const int* __restrict__ mask,
    float* __restrict__ out)
{
    extern __shared__ float sm[];
    float* s_compat = sm + O_COMPAT;
    float* s_buf    = sm + O_BUF;
    float* s_QT     = sm + O_QT;
    float* s_mean   = sm + O_MEAN;
    float* s_q      = sm + O_Q;
    float* s_ef     = sm + O_EF;
    float* s_el     = sm + O_EL;
    float* s_heads  = sm + O_HEADS;
    float* s_gl     = sm + O_GL;
    float* s_gt     = sm + O_GT;
    float* s_ebar   = sm + O_EBAR;
    float* s_red    = sm + O_RED;

    const int b = blockIdx.x, t = threadIdx.x;
    const int lane = t & 31, warp = t >> 5;
    const float* embB = emb + (size_t)b * NN * DD;
    const int* mkB = mask + (size_t)b * NN;

    float4 pr[4];   // prefetch registers: chunk = 256 rows x 32 dims
    // thread's 4 slots: i = k*512 + t; rl = i>>3 in [0,256), seg = i&7
    auto ldchunk = [&](int idx) {
        int T = idx >> 2, c = idx & 3;
        #pragma unroll
        for (int k = 0; k < 4; k++) {
            int i = (k << 9) + t;
            int rl = i >> 3, seg = i & 7;
            int gr = T * 256 + rl; if (gr > NN - 1) gr = NN - 1;
            pr[k] = *(const float4*)(embB + (size_t)gr * DD + c * 32 + seg * 4);
        }
    };
    auto stchunk = [&]() {
        #pragma unroll
        for (int k = 0; k < 4; k++) {
            int i = (k << 9) + t;
            int rl = i >> 3, seg = i & 7;
            *(float4*)(s_buf + rl * 36 + seg * 4) = pr[k];
        }
    };

    // prefetch phase-1 chunk 0 before phase 0
    ldchunk(0);

    // ---- Phase 0: mean (MLP=8) + first/last rows ----
    {
        int d = t & 127, g = t >> 7;
        const float* E = embB + d;
        float a0 = 0.f, a1 = 0.f, a2 = 0.f, a3 = 0.f;
        float a4 = 0.f, a5 = 0.f, a6 = 0.f, a7 = 0.f;
        int n = g;
        for (; n + 28 < NN; n += 32) {
            a0 += E[(size_t)n * DD];
            a1 += E[(size_t)(n + 4) * DD];
            a2 += E[(size_t)(n + 8) * DD];
            a3 += E[(size_t)(n + 12) * DD];
            a4 += E[(size_t)(n + 16) * DD];
            a5 += E[(size_t)(n + 20) * DD];
            a6 += E[(size_t)(n + 24) * DD];
            a7 += E[(size_t)(n + 28) * DD];
        }
        for (; n < NN; n += 4) a0 += E[(size_t)n * DD];
        s_compat[g * DD + d] = ((a0 + a1) + (a2 + a3)) + ((a4 + a5) + (a6 + a7));
    }
    if (t < DD)       s_ef[t] = embB[(size_t)fidx[b] * DD + t];
    else if (t < 256) s_el[t - DD] = embB[(size_t)lidx[b] * DD + (t - DD)];
    __syncthreads();
    if (t < DD)
        s_mean[t] = (s_compat[t] + s_compat[DD + t] + s_compat[2 * DD + t]
                     + s_compat[3 * DD + t]) * (1.0f / NN);
    __syncthreads();

    // ---- Phase 0b: q = mean@Wf + [ef;el]@Ws ----
    if (t < DD) {
        float acc = 0.f;
        #pragma unroll 4
        for (int i = 0; i < DD; i++) acc += s_mean[i] * Wf[i * DD + t];
        #pragma unroll 4
        for (int i = 0; i < DD; i++) acc += s_ef[i] * Ws[i * DD + t];
        #pragma unroll 4
        for (int i = 0; i < DD; i++) acc += s_el[i] * Ws[(DD + i) * DD + t];
        s_q[t] = acc;
    }
    __syncthreads();

    // ---- Phase 0c: qt[d][h] = 0.25 * W_K[d, h*16:+16] . q[h*16:+16] ----
    if (t < 256) {
        int d = t >> 1, h0 = (t & 1) * 4;
        #pragma unroll
        for (int h = h0; h < h0 + 4; h++) {
            const float* w = Wn + d * 384 + h * 16;
            const float* qq = s_q + h * 16;
            float acc = 0.f;
            #pragma unroll
            for (int k = 0; k < 16; k++) acc += w[k] * qq[k];
            s_QT[d * 8 + h] = acc * 0.25f;
        }
    }

    // ---- Phase 1: compat, reg-prefetch pipeline, 2 thr/row x 4 heads ----
    {
        const int r = t >> 1, q4 = t & 1;
        u64 acc01 = 0, acc23 = 0;
        for (int idx = 0; idx < 16; idx++) {
            __syncthreads();          // buf consumers of idx-1 done
            stchunk();                // publish chunk idx
            __syncthreads();
            if (idx < 15) ldchunk(idx + 1);   // LDGs overlap compute below
            const float* bp = s_buf + r * 36;
            const ulonglong2* qt2 = (const ulonglong2*)s_QT + q4;
            int c = idx & 3;
            #pragma unroll
            for (int j = 0; j < 8; j++) {
                float4 e = *(const float4*)(bp + j * 4);
                int d0 = (c * 32 + j * 4) * 2;
                ulonglong2 qa;
                qa = qt2[d0];     acc01 = fma2(packdup(e.x), qa.x, acc01);
                                  acc23 = fma2(packdup(e.x), qa.y, acc23);
                qa = qt2[d0 + 2]; acc01 = fma2(packdup(e.y), qa.x, acc01);
                                  acc23 = fma2(packdup(e.y), qa.y, acc23);
                qa = qt2[d0 + 4]; acc01 = fma2(packdup(e.z), qa.x, acc01);
                                  acc23 = fma2(packdup(e.z), qa.y, acc23);
                qa = qt2[d0 + 6]; acc01 = fma2(packdup(e.w), qa.x, acc01);
                                  acc23 = fma2(packdup(e.w), qa.y, acc23);
            }
            if (c == 3) {
                int row = (idx >> 2) * 256 + r;
                if (row < NN) {
                    int mk = mkB[row];
                    float2 p01 = unpack2(acc01), p23 = unpack2(acc23);
                    int hb = q4 * 4;
                    s_compat[(hb + 0) * NN + row] = mk ? NEGV : p01.x;
                    s_compat[(hb + 1) * NN + row] = mk ? NEGV : p01.y;
                    s_compat[(hb + 2) * NN + row] = mk ? NEGV : p23.x;
                    s_compat[(hb + 3) * NN + row] = mk ? NEGV : p23.y;
                }
                acc01 = 0; acc23 = 0;
            }
        }
    }
    __syncthreads();

    // ---- Phase 1b: per-head softmax, 2 warps per head ----
    {
        int h = warp >> 1, seg = warp & 1;
        const float* row = s_compat + h * NN;
        float mx = -1e30f;
        for (int n = seg * 32 + lane; n < NN; n += 64) mx = fmaxf(mx, row[n]);
        #pragma unroll
        for (int o = 16; o > 0; o >>= 1) mx = fmaxf(mx, __shfl_xor_sync(0xffffffffu, mx, o));
        if (lane == 0) s_red[warp] = mx;
        __syncthreads();
        float hm = fmaxf(s_red[2 * h], s_red[2 * h + 1]);
        float sme = 0.f;
        for (int n = seg * 32 + lane; n < NN; n += 64) sme += __expf(row[n] - hm);
        #pragma unroll
        for (int o = 16; o > 0; o >>= 1) sme += __shfl_xor_sync(0xffffffffu, sme, o);
        if (lane == 0) s_red[16 + warp] = sme;
        __syncthreads();
        float inv = 1.0f / (s_red[16 + 2 * h] + s_red[16 + 2 * h + 1]);
        for (int n = seg * 32 + lane; n < NN; n += 64)
            s_buf[n * 8 + h] = __expf(row[n] - hm) * inv;   // s_at[n][8]
    }
    __syncthreads();

    // ---- Phase 2: ebar, MLP=8, attn broadcast ----
    {
        int dim = t & 127, g = t >> 7;
        const float* E = embB + dim;
        u64 a0 = 0, a1 = 0, a2 = 0, a3 = 0;
        int n = g;
        for (; n + 28 < NN; n += 32) {
            float e0 = E[(size_t)n * DD];
            float e1 = E[(size_t)(n + 4) * DD];
            float e2 = E[(size_t)(n + 8) * DD];
            float e3 = E[(size_t)(n + 12) * DD];
            float e4 = E[(size_t)(n + 16) * DD];
            float e5 = E[(size_t)(n + 20) * DD];
            float e6 = E[(size_t)(n + 24) * DD];
            float e7 = E[(size_t)(n + 28) * DD];
            const u64* t0 = (const u64*)(s_buf + n * 8);
            const u64* t1 = (const u64*)(s_buf + (n + 4) * 8);
            const u64* t2 = (const u64*)(s_buf + (n + 8) * 8);
            const u64* t3 = (const u64*)(s_buf + (n + 12) * 8);
            const u64* t4 = (const u64*)(s_buf + (n + 16) * 8);
            const u64* t5 = (const u64*)(s_buf + (n + 20) * 8);
            const u64* t6 = (const u64*)(s_buf + (n + 24) * 8);
            const u64* t7 = (const u64*)(s_buf + (n + 28) * 8);
            u64 d0 = packdup(e0), d1 = packdup(e1), d2 = packdup(e2), d3 = packdup(e3);
            a0 = fma2(d0, t0[0], a0); a1 = fma2(d0, t0[1], a1);
            a2 = fma2(d0, t0[2], a2); a3 = fma2(d0, t0[3], a3);
            a0 = fma2(d1, t1[0], a0); a1 = fma2(d1, t1[1], a1);
            a2 = fma2(d1, t1[2], a2); a3 = fma2(d1, t1[3], a3);
            a0 = fma2(d2, t2[0], a0); a1 = fma2(d2, t2[1], a1);
            a2 = fma2(d2, t2[2], a2); a3 = fma2(d2, t2[3], a3);
            a0 = fma2(d3, t3[0], a0); a1 = fma2(d3, t3[1], a1);
            a2 = fma2(d3, t3[2], a2); a3 = fma2(d3, t3[3], a3);
            u64 d4 = packdup(e4), d5 = packdup(e5), d6 = packdup(e6), d7 = packdup(e7);
            a0 = fma2(d4, t4[0], a0); a1 = fma2(d4, t4[1], a1);
            a2 = fma2(d4, t4[2], a2); a3 = fma2(d4, t4[3], a3);
            a0 = fma2(d5, t5[0], a0); a1 = fma2(d5, t5[1], a1);
            a2 = fma2(d5, t5[2], a2); a3 = fma2(d5, t5[3], a3);
            a0 = fma2(d6, t6[0], a0); a1 = fma2(d6, t6[1], a1);
            a2 = fma2(d6, t6[2], a2); a3 = fma2(d6, t6[3], a3);
            a0 = fma2(d7, t7[0], a0); a1 = fma2(d7, t7[1], a1);
            a2 = fma2(d7, t7[2], a2); a3 = fma2(d7, t7[3], a3);
        }
        for (; n < NN; n += 4) {
            u64 ed = packdup(E[(size_t)n * DD]);
            const u64* at = (const u64*)(s_buf + n * 8);
            a0 = fma2(ed, at[0], a0); a1 = fma2(ed, at[1], a1);
            a2 = fma2(ed, at[2], a2); a3 = fma2(ed, at[3], a3);
        }
        __syncthreads();       // all s_at reads done; s_buf free
        ldchunk(0);            // prefetch phase-3 chunk 0
        float2 f0 = unpack2(a0), f1 = unpack2(a1), f2 = unpack2(a2), f3 = unpack2(a3);
        float* pp = s_compat + g * 1024 + dim;   // partials [g][h][128]
        pp[0] = f0.x; pp[128] = f0.y; pp[256] = f1.x; pp[384] = f1.y;
        pp[512] = f2.x; pp[640] = f2.y; pp[768] = f3.x; pp[896] = f3.y;
    }
    __syncthreads();
    {
        s_ebar[t] = (s_compat[t] + s_compat[1024 + t])
                  + (s_compat[2048 + t] + s_compat[3072 + t]);
        int i2 = t + 512;
        s_ebar[i2] = (s_compat[i2] + s_compat[1024 + i2])
                   + (s_compat[2048 + i2] + s_compat[3072 + i2]);
    }
    __syncthreads();

    // ---- Phase 2b: heads -> glimpse -> gtilde ----
    if (t < DD) {
        int h = t >> 4;
        const float* eb = s_ebar + h * DD;
        float acc = 0.f;
        #pragma unroll 4
        for (int d = 0; d < DD; d++) acc += eb[d] * Wn[d * 384 + 128 + t];
        s_heads[t] = acc;
    }
    __syncthreads();
    if (t < DD) {
        float acc = 0.f;
        #pragma unroll 4
        for (int i = 0; i < DD; i++) acc += s_heads[i] * Wo[i * DD + t];
        s_gl[t] = acc;
    }
    __syncthreads();
    if (t < DD) {
        const float* w = Wn + t * 384 + 256;
        float acc = 0.f;
        #pragma unroll 4
        for (int j = 0; j < DD; j++) acc += w[j] * s_gl[j];
        s_gt[t] = acc * 0.08838834764831845f;
    }
    __syncthreads();

    // ---- Phase 3: logits, reg-prefetch pipeline, 2 thr/row dim-split ----
    float* s_lg = s_compat;
    float lmax = -1e30f;
    {
        const int r = t >> 1, p = t & 1;
        u64 acc = 0;
        for (int idx = 0; idx < 16; idx++) {
            __syncthreads();
            stchunk();
            __syncthreads();
            if (idx < 15) ldchunk(idx + 1);
            const float* bp = s_buf + r * 36 + p * 16;
            int c = idx & 3;
            const u64* gtp = (const u64*)s_gt + c * 16 + p * 8;
            float4 e0 = *(const float4*)(bp);
            float4 e1 = *(const float4*)(bp + 4);
            float4 e2 = *(const float4*)(bp + 8);
            float4 e3 = *(const float4*)(bp + 12);
            acc = fma2(pack2(e0.x, e0.y), gtp[0], acc);
            acc = fma2(pack2(e0.z, e0.w), gtp[1], acc);
            acc = fma2(pack2(e1.x, e1.y), gtp[2], acc);
            acc = fma2(pack2(e1.z, e1.w), gtp[3], acc);
            acc = fma2(pack2(e2.x, e2.y), gtp[4], acc);
            acc = fma2(pack2(e2.z, e2.w), gtp[5], acc);
            acc = fma2(pack2(e3.x, e3.y), gtp[6], acc);
            acc = fma2(pack2(e3.z, e3.w), gtp[7], acc);
            if (c == 3) {
                float2 v = unpack2(acc);
                float s = v.x + v.y;
                s += __shfl_xor_sync(0xffffffffu, s, 1);
                int row = (idx >> 2) * 256 + r;
                if (p == 0 && row < NN) {
                    float vv = tanh_fast(s) * 10.0f;
                    if (mkB[row] != 0) vv = NEGV;
                    s_lg[row] = vv;
                    lmax = fmaxf(lmax, vv);
                }
                acc = 0;
            }
        }
    }
    __syncthreads();
    // ---- log-softmax over 1000 ----
    #pragma unroll
    for (int o = 16; o > 0; o >>= 1) lmax = fmaxf(lmax, __shfl_xor_sync(0xffffffffu, lmax, o));
    if (lane == 0) s_red[warp] = lmax;
    __syncthreads();
    float bmax = s_red[0];
    #pragma unroll
    for (int w = 1; w < 16; w++) bmax = fmaxf(bmax, s_red[w]);
    float ls = 0.f;
    for (int n = t; n < NN; n += 512) ls += __expf(s_lg[n] - bmax);
    #pragma unroll
    for (int o = 16; o > 0; o >>= 1) ls += __shfl_xor_sync(0xffffffffu, ls, o);
    if (lane == 0) s_red[16 + warp] = ls;
    __syncthreads();
    float tot = s_red[16];
    #pragma unroll
    for (int w = 1; w < 16; w++) tot += s_red[16 + w];
    float logZ = bmax + logf(tot);
    float* outB = out + (size_t)b * NN;
    for (int n = t; n < NN; n += 512) outB[n] = s_lg[n] - logZ;
}

extern "C" void kernel_launch(void* const* d_in, const int* in_sizes, int n_in,
                              void* d_out, int out_size) {
    const float* emb = (const float*)d_in[0];
    const float* Wn  = (const float*)d_in[1];
    const float* Wf  = (const float*)d_in[2];
    const float* Ws  = (const float*)d_in[3];
    const float* Wo  = (const float*)d_in[4];
    const int* fidx  = (const int*)d_in[5];
    const int* lidx  = (const int*)d_in[6];
    const int* mask  = (const int*)d_in[7];
    float* out = (float*)d_out;
    cudaFuncSetAttribute(attn_v6, cudaFuncAttributeMaxDynamicSharedMemorySize, SM_WORDS * 4);
    attn_v6<<<256, 512, SM_WORDS * 4>>>(emb, Wn, Wf, Ws, Wo, fidx, lidx, mask, out);
}